// round 2
// baseline (speedup 1.0000x reference)
#include <cuda_runtime.h>
#include <cstdint>

// CenterLoss: loss = mean_b clamp(||x_b - centers[label_b]||^2, 1e-12, 1e12)
//             + (C-1)*1e-12   (masked zeros clamped to 1e-12 in the reference)

#define FEAT_DIM 512
#define TPB 128          // 128 threads * float4 = 512 features exactly

__device__ float g_partials[8192];   // >= BATCH (4096)
__device__ int   g_labels_are_i64;   // runtime-detected label dtype

// Probe: if labels are int64 (values < 2^31), every odd 32-bit word is 0.
__global__ void detect_label_dtype_kernel(const int* __restrict__ lab32, int B)
{
    const int t = threadIdx.x;          // 32 threads
    // sample 32 odd words spread across the buffer (when viewed as int32 pairs)
    int idx = 2 * ((t * (B / 32)) % B) + 1;
    int v = lab32[idx];                 // safe: buffer holds >= B int32s either way
    unsigned allzero = __ballot_sync(0xffffffffu, v == 0);
    if (t == 0) g_labels_are_i64 = (allzero == 0xffffffffu) ? 1 : 0;
}

__global__ void __launch_bounds__(TPB)
center_loss_dist_kernel(const float* __restrict__ x,
                        const void* __restrict__ labels,
                        const float* __restrict__ centers,
                        int C)
{
    const int b = blockIdx.x;
    const int t = threadIdx.x;

    long long lbl;
    if (g_labels_are_i64)
        lbl = ((const long long*)labels)[b];
    else
        lbl = ((const int*)labels)[b];
    // defensive clamp: never OOB, wrong answers show up as rel_err not segfault
    if (lbl < 0) lbl = 0;
    if (lbl >= C) lbl = C - 1;

    const float4* __restrict__ xr = reinterpret_cast<const float4*>(x + (size_t)b * FEAT_DIM);
    const float4* __restrict__ cr = reinterpret_cast<const float4*>(centers + (size_t)lbl * FEAT_DIM);

    const float4 xv = xr[t];
    const float4 cv = cr[t];

    const float d0 = xv.x - cv.x;
    const float d1 = xv.y - cv.y;
    const float d2 = xv.z - cv.z;
    const float d3 = xv.w - cv.w;
    float s = d0 * d0 + d1 * d1 + d2 * d2 + d3 * d3;

    #pragma unroll
    for (int o = 16; o > 0; o >>= 1)
        s += __shfl_xor_sync(0xffffffffu, s, o);

    __shared__ float ws[TPB / 32];
    if ((t & 31) == 0) ws[t >> 5] = s;
    __syncthreads();

    if (t == 0) {
        float tot = ws[0] + ws[1] + ws[2] + ws[3];
        tot = fminf(fmaxf(tot, 1e-12f), 1e12f);   // clamp (per reference)
        g_partials[b] = tot;
    }
}

__global__ void __launch_bounds__(1024)
center_loss_final_kernel(float* __restrict__ out, int B, int C)
{
    const int t = threadIdx.x;

    float s = 0.0f;
    for (int i = t; i < B; i += 1024)
        s += g_partials[i];

    #pragma unroll
    for (int o = 16; o > 0; o >>= 1)
        s += __shfl_xor_sync(0xffffffffu, s, o);

    __shared__ float ws[32];
    if ((t & 31) == 0) ws[t >> 5] = s;
    __syncthreads();

    if (t < 32) {
        float v = ws[t];
        #pragma unroll
        for (int o = 16; o > 0; o >>= 1)
            v += __shfl_xor_sync(0xffffffffu, v, o);
        if (t == 0) {
            // mean over batch + contribution of the (C-1) clamped zeros per row
            out[0] = v / (float)B + (float)(C - 1) * 1e-12f;
        }
    }
}

extern "C" void kernel_launch(void* const* d_in, const int* in_sizes, int n_in,
                              void* d_out, int out_size)
{
    const float* x       = (const float*)d_in[0];
    const void*  labels  = d_in[1];
    const float* centers = (const float*)d_in[2];
    float*       out     = (float*)d_out;

    const int B = in_sizes[1];                   // 4096
    const int C = in_sizes[2] / FEAT_DIM;        // 10000

    detect_label_dtype_kernel<<<1, 32>>>((const int*)labels, B);
    center_loss_dist_kernel<<<B, TPB>>>(x, labels, centers, C);
    center_loss_final_kernel<<<1, 1024>>>(out, B, C);
}

// round 3
// speedup vs baseline: 1.0126x; 1.0126x over previous
#include <cuda_runtime.h>
#include <cstdint>

// CenterLoss: loss = mean_b clamp(||x_b - centers[label_b]||^2, 1e-12, 1e12)
//             + (C-1)*1e-12   (masked zeros clamped to 1e-12 in the reference)
// labels arrive as int32 (harness maps int64 -> int32; established in R1/R2).

#define FEAT_DIM 512
#define TPB 256                    // 8 warps = 8 samples per block
#define SAMPLES_PER_BLOCK 8

__device__ float    g_partials[8192];   // >= BATCH (4096)
__device__ unsigned g_done = 0;         // last-block counter (self-resetting)

__global__ void __launch_bounds__(TPB)
center_loss_fused_kernel(const float* __restrict__ x,
                         const int*   __restrict__ labels,
                         const float* __restrict__ centers,
                         float* __restrict__ out,
                         int B, int C)
{
    const int warp = threadIdx.x >> 5;
    const int lane = threadIdx.x & 31;
    const int b    = blockIdx.x * SAMPLES_PER_BLOCK + warp;   // sample index

    // ---- per-warp: squared distance of one sample ----
    int lbl = labels[b];
    lbl = min(max(lbl, 0), C - 1);      // defensive: never OOB

    const float4* __restrict__ xr = reinterpret_cast<const float4*>(x + (size_t)b * FEAT_DIM);
    const float4* __restrict__ cr = reinterpret_cast<const float4*>(centers + (size_t)lbl * FEAT_DIM);

    // lane handles 16 consecutive floats = 4 float4 pairs (8 independent loads)
    float s = 0.0f;
    #pragma unroll
    for (int i = 0; i < 4; i++) {
        const float4 xv = xr[lane * 4 + i];
        const float4 cv = cr[lane * 4 + i];
        const float d0 = xv.x - cv.x;
        const float d1 = xv.y - cv.y;
        const float d2 = xv.z - cv.z;
        const float d3 = xv.w - cv.w;
        s += d0 * d0 + d1 * d1 + d2 * d2 + d3 * d3;
    }

    #pragma unroll
    for (int o = 16; o > 0; o >>= 1)
        s += __shfl_xor_sync(0xffffffffu, s, o);

    if (lane == 0) {
        s = fminf(fmaxf(s, 1e-12f), 1e12f);   // clamp (per reference)
        g_partials[b] = s;
    }

    // ---- last-block reduction ----
    __shared__ bool s_last;
    __threadfence();                         // partials visible before counter bump
    __syncthreads();                         // all 8 partials of this block written
    if (threadIdx.x == 0) {
        unsigned v = atomicAdd(&g_done, 1u);
        s_last = (v == gridDim.x - 1);
    }
    __syncthreads();
    if (!s_last) return;

    // this block is last: all partials are globally visible (fence+atomic chain)
    float acc = 0.0f;
    for (int i = threadIdx.x; i < B; i += TPB)
        acc += g_partials[i];

    #pragma unroll
    for (int o = 16; o > 0; o >>= 1)
        acc += __shfl_xor_sync(0xffffffffu, acc, o);

    __shared__ float ws[TPB / 32];
    if (lane == 0) ws[warp] = acc;
    __syncthreads();

    if (threadIdx.x == 0) {
        float tot = 0.0f;
        #pragma unroll
        for (int i = 0; i < TPB / 32; i++) tot += ws[i];
        out[0] = tot / (float)B + (float)(C - 1) * 1e-12f;
        g_done = 0;                          // reset for next graph replay
    }
}

extern "C" void kernel_launch(void* const* d_in, const int* in_sizes, int n_in,
                              void* d_out, int out_size)
{
    const float* x       = (const float*)d_in[0];
    const int*   labels  = (const int*)d_in[1];
    const float* centers = (const float*)d_in[2];
    float*       out     = (float*)d_out;

    const int B = in_sizes[1];                 // 4096
    const int C = in_sizes[2] / FEAT_DIM;      // 10000

    center_loss_fused_kernel<<<B / SAMPLES_PER_BLOCK, TPB>>>(x, labels, centers, out, B, C);
}

// round 4
// speedup vs baseline: 1.1630x; 1.1486x over previous
#include <cuda_runtime.h>
#include <cstdint>

// CenterLoss: loss = mean_b clamp(||x_b - centers[label_b]||^2, 1e-12, 1e12)
//             + (C-1)*1e-12   (masked zeros clamped to 1e-12 in the reference)
// labels arrive as int32 (harness maps int64 -> int32; established in R1/R2).

#define FEAT_DIM 512
#define TPB 256                    // 8 warps = 8 samples per block
#define SAMPLES_PER_BLOCK 8

__device__ float    g_partials[8192];   // >= BATCH (4096)
__device__ unsigned g_done = 0;         // last-block counter (self-resetting)

__global__ void __launch_bounds__(TPB)
center_loss_fused_kernel(const float* __restrict__ x,
                         const int*   __restrict__ labels,
                         const float* __restrict__ centers,
                         float* __restrict__ out,
                         int B, int C)
{
    const int warp = threadIdx.x >> 5;
    const int lane = threadIdx.x & 31;
    const int b    = blockIdx.x * SAMPLES_PER_BLOCK + warp;   // sample index

    // ---- per-warp: squared distance of one sample ----
    int lbl = labels[b];
    lbl = min(max(lbl, 0), C - 1);      // defensive: never OOB

    const float4* __restrict__ xr = reinterpret_cast<const float4*>(x + (size_t)b * FEAT_DIM);
    const float4* __restrict__ cr = reinterpret_cast<const float4*>(centers + (size_t)lbl * FEAT_DIM);

    // COALESCED: per iteration, lanes cover 512 contiguous bytes (4 lines exactly).
    float s = 0.0f;
    #pragma unroll
    for (int i = 0; i < 4; i++) {
        const float4 xv = xr[lane + 32 * i];
        const float4 cv = cr[lane + 32 * i];
        const float d0 = xv.x - cv.x;
        const float d1 = xv.y - cv.y;
        const float d2 = xv.z - cv.z;
        const float d3 = xv.w - cv.w;
        s += d0 * d0 + d1 * d1 + d2 * d2 + d3 * d3;
    }

    #pragma unroll
    for (int o = 16; o > 0; o >>= 1)
        s += __shfl_xor_sync(0xffffffffu, s, o);

    if (lane == 0) {
        s = fminf(fmaxf(s, 1e-12f), 1e12f);   // clamp (per reference)
        g_partials[b] = s;
    }

    // ---- last-block reduction ----
    __shared__ bool s_last;
    __threadfence();                         // partials visible before counter bump
    __syncthreads();                         // all 8 partials of this block written
    if (threadIdx.x == 0) {
        unsigned v = atomicAdd(&g_done, 1u);
        s_last = (v == gridDim.x - 1);
    }
    __syncthreads();
    if (!s_last) return;

    // this block is last: all partials are globally visible (fence+atomic chain)
    float acc = 0.0f;
    for (int i = threadIdx.x; i < B; i += TPB)
        acc += g_partials[i];

    #pragma unroll
    for (int o = 16; o > 0; o >>= 1)
        acc += __shfl_xor_sync(0xffffffffu, acc, o);

    __shared__ float ws[TPB / 32];
    if (lane == 0) ws[warp] = acc;
    __syncthreads();

    if (threadIdx.x == 0) {
        float tot = 0.0f;
        #pragma unroll
        for (int i = 0; i < TPB / 32; i++) tot += ws[i];
        out[0] = tot / (float)B + (float)(C - 1) * 1e-12f;
        g_done = 0;                          // reset for next graph replay
    }
}

extern "C" void kernel_launch(void* const* d_in, const int* in_sizes, int n_in,
                              void* d_out, int out_size)
{
    const float* x       = (const float*)d_in[0];
    const int*   labels  = (const int*)d_in[1];
    const float* centers = (const float*)d_in[2];
    float*       out     = (float*)d_out;

    const int B = in_sizes[1];                 // 4096
    const int C = in_sizes[2] / FEAT_DIM;      // 10000

    center_loss_fused_kernel<<<B / SAMPLES_PER_BLOCK, TPB>>>(x, labels, centers, out, B, C);
}

// round 5
// speedup vs baseline: 1.2205x; 1.0494x over previous
#include <cuda_runtime.h>
#include <cstdint>

// CenterLoss: loss = mean_b clamp(||x_b - centers[label_b]||^2, 1e-12, 1e12)
//             + (C-1)*1e-12   (masked zeros clamped to 1e-12 in the reference)
// labels arrive as int32 (harness maps int64 -> int32; established in R1/R2).

#define FEAT_DIM 512
#define TPB 256                 // 8 warps = 4 samples (2 warps per sample)
#define SAMPLES_PER_BLOCK 4

__device__ __align__(16) float g_partials[8192];   // one per block (1024 used)
__device__ unsigned g_done = 0;                    // last-block counter (self-resetting)

__global__ void __launch_bounds__(TPB)
center_loss_fused_kernel(const float* __restrict__ x,
                         const int*   __restrict__ labels,
                         const float* __restrict__ centers,
                         float* __restrict__ out,
                         int B, int C)
{
    const int tid   = threadIdx.x;
    const int wid   = tid >> 5;          // 0..7
    const int lane  = tid & 31;
    const int g64   = tid & 63;          // lane within 64-thread sample group
    const int b     = blockIdx.x * SAMPLES_PER_BLOCK + (tid >> 6);

    // ---- per-sample (2 warps): squared distance ----
    int lbl = labels[b];                 // broadcast load (same addr per group)
    lbl = min(max(lbl, 0), C - 1);       // defensive: never OOB

    const float4* __restrict__ xr = reinterpret_cast<const float4*>(x + (size_t)b * FEAT_DIM);
    const float4* __restrict__ cr = reinterpret_cast<const float4*>(centers + (size_t)lbl * FEAT_DIM);

    // 128 float4 per sample over 64 lanes: each lane takes g64 and g64+64.
    // Fully coalesced: 64 consecutive float4 = 1 KB contiguous per half.
    const float4 xv0 = xr[g64];
    const float4 cv0 = cr[g64];
    const float4 xv1 = xr[g64 + 64];
    const float4 cv1 = cr[g64 + 64];

    float d0 = xv0.x - cv0.x, d1 = xv0.y - cv0.y, d2 = xv0.z - cv0.z, d3 = xv0.w - cv0.w;
    float s  = d0 * d0 + d1 * d1 + d2 * d2 + d3 * d3;
    d0 = xv1.x - cv1.x; d1 = xv1.y - cv1.y; d2 = xv1.z - cv1.z; d3 = xv1.w - cv1.w;
    s += d0 * d0 + d1 * d1 + d2 * d2 + d3 * d3;

    #pragma unroll
    for (int o = 16; o > 0; o >>= 1)
        s += __shfl_xor_sync(0xffffffffu, s, o);

    __shared__ float s_warp[8];          // one partial per warp
    __shared__ bool  s_last;
    if (lane == 0) s_warp[wid] = s;
    __syncthreads();

    // ---- block: combine 2 warps/sample, clamp per sample, one partial per block ----
    if (tid == 0) {
        float tot = 0.0f;
        #pragma unroll
        for (int i = 0; i < SAMPLES_PER_BLOCK; i++) {
            float d = s_warp[2 * i] + s_warp[2 * i + 1];
            tot += fminf(fmaxf(d, 1e-12f), 1e12f);   // clamp per reference
        }
        g_partials[blockIdx.x] = tot;
        __threadfence();                 // partial visible before counter bump
        unsigned v = atomicAdd(&g_done, 1u);
        s_last = (v == gridDim.x - 1);
    }
    __syncthreads();
    if (!s_last) return;

    // ---- last block: reduce gridDim.x partials (one float4 per thread) ----
    const int nq = gridDim.x >> 2;       // 1024/4 = 256 float4
    float acc = 0.0f;
    for (int i = tid; i < nq; i += TPB) {
        float4 v = reinterpret_cast<const float4*>(g_partials)[i];
        acc += v.x + v.y + v.z + v.w;
    }

    #pragma unroll
    for (int o = 16; o > 0; o >>= 1)
        acc += __shfl_xor_sync(0xffffffffu, acc, o);

    __shared__ float ws[8];
    if (lane == 0) ws[wid] = acc;
    __syncthreads();

    if (tid == 0) {
        float tot = 0.0f;
        #pragma unroll
        for (int i = 0; i < 8; i++) tot += ws[i];
        out[0] = tot / (float)B + (float)(C - 1) * 1e-12f;
        g_done = 0;                      // reset for next graph replay
    }
}

extern "C" void kernel_launch(void* const* d_in, const int* in_sizes, int n_in,
                              void* d_out, int out_size)
{
    const float* x       = (const float*)d_in[0];
    const int*   labels  = (const int*)d_in[1];
    const float* centers = (const float*)d_in[2];
    float*       out     = (float*)d_out;

    const int B = in_sizes[1];                 // 4096
    const int C = in_sizes[2] / FEAT_DIM;      // 10000

    center_loss_fused_kernel<<<B / SAMPLES_PER_BLOCK, TPB>>>(x, labels, centers, out, B, C);
}

// round 6
// speedup vs baseline: 1.2490x; 1.0233x over previous
#include <cuda_runtime.h>
#include <cstdint>

// CenterLoss: loss = mean_b clamp(||x_b - centers[label_b]||^2, 1e-12, 1e12)
//             + (C-1)*1e-12   (masked zeros clamped to 1e-12 in the reference)
// labels arrive as int32 (harness maps int64 -> int32; established in R1/R2).
// R6: bulk loads via cp.async.cg (LDGSTS) to escape the per-SM outstanding-LDG
//     cap that pinned DRAM throughput at ~1.7 TB/s in R3-R5.

#define FEAT_DIM 512
#define TPB 256                 // 8 warps = 4 samples (2 warps per sample)
#define SAMPLES_PER_BLOCK 4

__device__ __align__(16) float g_partials[8192];   // one per block (1024 used)
__device__ unsigned g_done = 0;                    // last-block counter (self-resetting)

__device__ __forceinline__ void cp_async16(uint32_t smem_addr, const void* gptr)
{
    asm volatile("cp.async.cg.shared.global [%0], [%1], 16;\n"
                 :: "r"(smem_addr), "l"(gptr) : "memory");
}

__global__ void __launch_bounds__(TPB)
center_loss_fused_kernel(const float* __restrict__ x,
                         const int*   __restrict__ labels,
                         const float* __restrict__ centers,
                         float* __restrict__ out,
                         int B, int C)
{
    __shared__ __align__(16) float4 s_x[SAMPLES_PER_BLOCK][FEAT_DIM / 4];  // 8 KB
    __shared__ __align__(16) float4 s_c[SAMPLES_PER_BLOCK][FEAT_DIM / 4];  // 8 KB
    __shared__ float s_warp[8];
    __shared__ bool  s_last;

    const int tid  = threadIdx.x;
    const int wid  = tid >> 5;
    const int lane = tid & 31;
    const int g    = tid >> 6;           // sample group 0..3
    const int g64  = tid & 63;           // lane within 64-thread sample group
    const int b    = blockIdx.x * SAMPLES_PER_BLOCK + g;

    int lbl = labels[b];
    lbl = min(max(lbl, 0), C - 1);       // defensive: never OOB

    const float4* __restrict__ xr = reinterpret_cast<const float4*>(x + (size_t)b * FEAT_DIM);
    const float4* __restrict__ cr = reinterpret_cast<const float4*>(centers + (size_t)lbl * FEAT_DIM);

    // Fire-and-forget bulk copies: 4 x 16B per thread, perfectly coalesced
    // (64 consecutive float4 = 1 KB contiguous per group-half).
    const uint32_t sx0 = (uint32_t)__cvta_generic_to_shared(&s_x[g][g64]);
    const uint32_t sx1 = (uint32_t)__cvta_generic_to_shared(&s_x[g][g64 + 64]);
    const uint32_t sc0 = (uint32_t)__cvta_generic_to_shared(&s_c[g][g64]);
    const uint32_t sc1 = (uint32_t)__cvta_generic_to_shared(&s_c[g][g64 + 64]);
    cp_async16(sx0, xr + g64);
    cp_async16(sx1, xr + g64 + 64);
    cp_async16(sc0, cr + g64);
    cp_async16(sc1, cr + g64 + 64);
    asm volatile("cp.async.commit_group;\n" ::: "memory");
    asm volatile("cp.async.wait_group 0;\n" ::: "memory");
    // Each thread consumes only the smem bytes it copied itself -> no barrier.

    const float4 xv0 = s_x[g][g64];
    const float4 cv0 = s_c[g][g64];
    const float4 xv1 = s_x[g][g64 + 64];
    const float4 cv1 = s_c[g][g64 + 64];

    float d0 = xv0.x - cv0.x, d1 = xv0.y - cv0.y, d2 = xv0.z - cv0.z, d3 = xv0.w - cv0.w;
    float s  = d0 * d0 + d1 * d1 + d2 * d2 + d3 * d3;
    d0 = xv1.x - cv1.x; d1 = xv1.y - cv1.y; d2 = xv1.z - cv1.z; d3 = xv1.w - cv1.w;
    s += d0 * d0 + d1 * d1 + d2 * d2 + d3 * d3;

    #pragma unroll
    for (int o = 16; o > 0; o >>= 1)
        s += __shfl_xor_sync(0xffffffffu, s, o);

    if (lane == 0) s_warp[wid] = s;
    __syncthreads();

    // ---- block: combine 2 warps/sample, clamp per sample, one partial per block ----
    if (tid == 0) {
        float tot = 0.0f;
        #pragma unroll
        for (int i = 0; i < SAMPLES_PER_BLOCK; i++) {
            float d = s_warp[2 * i] + s_warp[2 * i + 1];
            tot += fminf(fmaxf(d, 1e-12f), 1e12f);   // clamp per reference
        }
        g_partials[blockIdx.x] = tot;
        __threadfence();                 // partial visible before counter bump
        unsigned v = atomicAdd(&g_done, 1u);
        s_last = (v == gridDim.x - 1);
    }
    __syncthreads();
    if (!s_last) return;

    // ---- last block: reduce gridDim.x partials (one float4 per thread) ----
    const int nq = gridDim.x >> 2;       // 1024/4 = 256 float4
    float acc = 0.0f;
    for (int i = tid; i < nq; i += TPB) {
        float4 v = reinterpret_cast<const float4*>(g_partials)[i];
        acc += v.x + v.y + v.z + v.w;
    }

    #pragma unroll
    for (int o = 16; o > 0; o >>= 1)
        acc += __shfl_xor_sync(0xffffffffu, acc, o);

    __shared__ float ws[8];
    if (lane == 0) ws[wid] = acc;
    __syncthreads();

    if (tid == 0) {
        float tot = 0.0f;
        #pragma unroll
        for (int i = 0; i < 8; i++) tot += ws[i];
        out[0] = tot / (float)B + (float)(C - 1) * 1e-12f;
        g_done = 0;                      // reset for next graph replay
    }
}

extern "C" void kernel_launch(void* const* d_in, const int* in_sizes, int n_in,
                              void* d_out, int out_size)
{
    const float* x       = (const float*)d_in[0];
    const int*   labels  = (const int*)d_in[1];
    const float* centers = (const float*)d_in[2];
    float*       out     = (float*)d_out;

    const int B = in_sizes[1];                 // 4096
    const int C = in_sizes[2] / FEAT_DIM;      // 10000

    center_loss_fused_kernel<<<B / SAMPLES_PER_BLOCK, TPB>>>(x, labels, centers, out, B, C);
}